// round 2
// baseline (speedup 1.0000x reference)
#include <cuda_runtime.h>
#include <math.h>

#define HW        (1 << 20)      // pixels per channel (1024*1024)
#define NCH       48             // B*C = 16*3
#define CHUNK     12             // channels per L2-resident chunk (50 MB)
#define NCHUNKS   (NCH / CHUNK)
#define NBINS     8192           // coarse histogram bins over [0,1]
#define CAP       8192           // gather capacity per (channel, percentile)
#define GAMMA_F   0.45454547f    // (float)(1.0/2.2)

// ---------------- scratch (device globals; no allocation allowed) ----------
__device__ unsigned int g_hist[NCH * NBINS];   // coarse hist of valid pixels
__device__ unsigned int g_n[NCH];              // valid-pixel count
__device__ int          g_bin[NCH * 2];        // coarse bin holding kth value
__device__ unsigned int g_off[NCH * 2];        // rank offset within that bin
__device__ unsigned int g_cnt[NCH * 2];        // gathered count
__device__ float        g_vals[NCH * 2 * CAP]; // gathered candidate values
__device__ float        g_v[NCH * 2];          // exact v2 / v98 per channel

__constant__ float c_A[3] = {1.0f / 0.229f, 1.0f / 0.224f, 1.0f / 0.225f};
__constant__ float c_B[3] = {-0.485f / 0.229f, -0.456f / 0.224f, -0.406f / 0.225f};

// ---------------- K0: zero scratch ------------------------------------------
__global__ void k_zero() {
    int i = blockIdx.x * blockDim.x + threadIdx.x;
    int stride = gridDim.x * blockDim.x;
    for (int j = i; j < NCH * NBINS; j += stride) g_hist[j] = 0;
    if (i < NCH * 2) g_cnt[i] = 0;
}

__device__ __forceinline__ int bin_of(float v) {
    int b = (int)(v * (float)NBINS);
    return b > (NBINS - 1) ? (NBINS - 1) : b;   // v > 1e-4 => b >= 0
}

// ---------------- K1: coarse histogram (DRAM read, fills L2) ----------------
__global__ void __launch_bounds__(256) k_hist(const float* __restrict__ x, int ch0) {
    __shared__ unsigned int sh[NBINS];
    const int ch = ch0 + blockIdx.y;
    const float4* p = (const float4*)(x + (size_t)ch * HW);
    const int nvec = HW / 4;
    const int per_block = nvec / gridDim.x;
    const int base = blockIdx.x * per_block;

    for (int i = threadIdx.x; i < NBINS; i += blockDim.x) sh[i] = 0;
    __syncthreads();

    #pragma unroll 8
    for (int i = threadIdx.x; i < per_block; i += blockDim.x) {
        float4 v = p[base + i];
        if (v.x > 1e-4f) atomicAdd(&sh[bin_of(v.x)], 1u);
        if (v.y > 1e-4f) atomicAdd(&sh[bin_of(v.y)], 1u);
        if (v.z > 1e-4f) atomicAdd(&sh[bin_of(v.z)], 1u);
        if (v.w > 1e-4f) atomicAdd(&sh[bin_of(v.w)], 1u);
    }
    __syncthreads();

    for (int i = threadIdx.x; i < NBINS; i += blockDim.x) {
        unsigned int c = sh[i];
        if (c) atomicAdd(&g_hist[ch * NBINS + i], c);
    }
}

// ---------------- K2: find coarse bin + offset for both ranks ---------------
__global__ void __launch_bounds__(256) k_select(int ch0) {
    const int ch = ch0 + blockIdx.x;
    __shared__ unsigned int part[256];
    __shared__ unsigned int excl[256];
    __shared__ unsigned int sh_n;
    __shared__ unsigned int r[2];

    const int t = threadIdx.x;
    const int BPT = NBINS / 256;   // 32 bins per thread
    unsigned int s = 0;
    for (int j = 0; j < BPT; j++) s += g_hist[ch * NBINS + t * BPT + j];
    part[t] = s;
    __syncthreads();

    if (t == 0) {
        unsigned int run = 0;
        for (int i = 0; i < 256; i++) { excl[i] = run; run += part[i]; }
        unsigned int n = run;
        sh_n = n;
        g_n[ch] = n;
        if (n == 0) {
            g_bin[ch * 2] = -1; g_bin[ch * 2 + 1] = -1;
            r[0] = 0; r[1] = 0;
        } else {
            unsigned long long k2  = (2ull  * n) / 100ull + 1ull; if (k2  > n) k2  = n;
            unsigned long long k98 = (98ull * n) / 100ull + 1ull; if (k98 > n) k98 = n;
            r[0] = (unsigned int)(k2 - 1);
            r[1] = (unsigned int)(k98 - 1);
        }
    }
    __syncthreads();
    if (sh_n == 0) return;

    for (int w = 0; w < 2; w++) {
        unsigned int rk = r[w];
        if (rk >= excl[t] && rk < excl[t] + part[t]) {
            unsigned int run = excl[t];
            for (int j = 0; j < BPT; j++) {
                unsigned int h = g_hist[ch * NBINS + t * BPT + j];
                if (rk < run + h) {
                    g_bin[ch * 2 + w] = t * BPT + j;
                    g_off[ch * 2 + w] = rk - run;
                    break;
                }
                run += h;
            }
        }
    }
}

// ---------------- K3: gather candidates (should hit L2) ---------------------
__global__ void __launch_bounds__(256) k_gather(const float* __restrict__ x, int ch0) {
    const int ch = ch0 + blockIdx.y;
    const int b2  = g_bin[ch * 2];
    const int b98 = g_bin[ch * 2 + 1];
    const float4* p = (const float4*)(x + (size_t)ch * HW);
    const int nvec = HW / 4;
    const int stride = gridDim.x * blockDim.x;

    #pragma unroll 4
    for (int i = blockIdx.x * blockDim.x + threadIdx.x; i < nvec; i += stride) {
        float4 v = p[i];
        float a0 = v.x, a1 = v.y, a2 = v.z, a3 = v.w;
        #pragma unroll
        for (int j = 0; j < 4; j++) {
            float f = (j == 0) ? a0 : (j == 1) ? a1 : (j == 2) ? a2 : a3;
            if (f > 1e-4f) {
                int b = bin_of(f);
                if (b == b2) {
                    unsigned int pz = atomicAdd(&g_cnt[ch * 2], 1u);
                    if (pz < CAP) g_vals[(size_t)(ch * 2) * CAP + pz] = f;
                }
                if (b == b98) {
                    unsigned int pz = atomicAdd(&g_cnt[ch * 2 + 1], 1u);
                    if (pz < CAP) g_vals[(size_t)(ch * 2 + 1) * CAP + pz] = f;
                }
            }
        }
    }
}

// ---------------- K3b: exact rank-select among gathered values --------------
__global__ void __launch_bounds__(256) k_kth(int ch0) {
    const int slot = ch0 * 2 + blockIdx.x;   // (ch, which)
    __shared__ float sv[CAP];
    const int bin = g_bin[slot];
    if (bin < 0) {                       // n == 0 -> value unused anyway
        if (threadIdx.x == 0) g_v[slot] = (slot & 1) ? 1.0f : 0.0f;
        return;
    }
    const unsigned int cnt = g_cnt[slot];
    const unsigned int m   = cnt < CAP ? cnt : CAP;
    const unsigned int off = g_off[slot];

    for (unsigned int i = threadIdx.x; i < m; i += blockDim.x)
        sv[i] = g_vals[(size_t)slot * CAP + i];
    __syncthreads();

    if (off >= m) {                      // overflow fallback (won't trigger here)
        if (threadIdx.x == 0)
            g_v[slot] = ((float)bin + (cnt ? (float)off / (float)cnt : 0.5f)) / (float)NBINS;
        return;
    }
    for (unsigned int i = threadIdx.x; i < m; i += blockDim.x) {
        float vi = sv[i];
        unsigned int less = 0, eqb = 0;
        for (unsigned int j = 0; j < m; j++) {
            float vj = sv[j];
            less += (vj < vi);
            eqb  += (vj == vi) && (j < i);
        }
        if (less + eqb == off) g_v[slot] = vi;   // exactly one writer
    }
}

// ---------------- K4: fused normalize + gamma + ImageNet --------------------
__device__ __forceinline__ float fastpow_g(float y) {
    float l, e;
    asm("lg2.approx.f32 %0, %1;" : "=f"(l) : "f"(y));
    asm("ex2.approx.f32 %0, %1;" : "=f"(e) : "f"(l * GAMMA_F));
    return e;
}

__global__ void __launch_bounds__(256) k_norm(const float* __restrict__ x,
                                              float* __restrict__ out, int ch0) {
    const int ch = ch0 + blockIdx.y;
    const int c  = ch - (ch / 3) * 3;
    const unsigned int n = g_n[ch];
    const float v2  = g_v[ch * 2];
    const float v98 = g_v[ch * 2 + 1];
    const float minv = (n > 100u) ? v2  : 0.0f;
    const float maxv = (n > 100u) ? v98 : 1.0f;
    float scale = maxv - minv;
    if (scale < 1e-6f) scale = 1e-6f;
    const float inv = 1.0f / scale;
    const float A = c_A[c], Bc = c_B[c];

    const float4* p = (const float4*)(x + (size_t)ch * HW);
    float4* q = (float4*)(out + (size_t)ch * HW);
    const int nvec = HW / 4;
    const int stride = gridDim.x * blockDim.x;

    #pragma unroll 4
    for (int i = blockIdx.x * blockDim.x + threadIdx.x; i < nvec; i += stride) {
        float4 v = p[i];
        float y0 = fminf(fmaxf((v.x - minv) * inv, 0.0f), 1.0f);
        float y1 = fminf(fmaxf((v.y - minv) * inv, 0.0f), 1.0f);
        float y2 = fminf(fmaxf((v.z - minv) * inv, 0.0f), 1.0f);
        float y3 = fminf(fmaxf((v.w - minv) * inv, 0.0f), 1.0f);
        float g0 = (y0 > 0.0f) ? fastpow_g(y0) : 0.0f;
        float g1 = (y1 > 0.0f) ? fastpow_g(y1) : 0.0f;
        float g2 = (y2 > 0.0f) ? fastpow_g(y2) : 0.0f;
        float g3 = (y3 > 0.0f) ? fastpow_g(y3) : 0.0f;
        float4 o;
        o.x = fmaf(g0, A, Bc);
        o.y = fmaf(g1, A, Bc);
        o.z = fmaf(g2, A, Bc);
        o.w = fmaf(g3, A, Bc);
        q[i] = o;
    }
}

// ---------------- launch ----------------------------------------------------
extern "C" void kernel_launch(void* const* d_in, const int* in_sizes, int n_in,
                              void* d_out, int out_size) {
    const float* x = (const float*)d_in[0];
    float* out = (float*)d_out;
    (void)in_sizes; (void)n_in; (void)out_size;

    k_zero<<<384, 256>>>();

    for (int c = 0; c < NCHUNKS; c++) {
        const int ch0 = c * CHUNK;
        // hist streams chunk from DRAM -> L2; gather + norm re-read from L2
        k_hist  <<<dim3(16,  CHUNK), 256>>>(x, ch0);
        k_select<<<CHUNK, 256>>>(ch0);
        k_gather<<<dim3(32,  CHUNK), 256>>>(x, ch0);
        k_kth   <<<CHUNK * 2, 256>>>(ch0);
        k_norm  <<<dim3(128, CHUNK), 256>>>(x, out, ch0);
    }
}

// round 3
// speedup vs baseline: 1.9402x; 1.9402x over previous
#include <cuda_runtime.h>
#include <math.h>

#define HW        (1 << 20)      // pixels per channel (1024*1024)
#define NVEC      (HW / 4)       // float4 per channel = 262144
#define NCH       48             // B*C = 16*3
#define NBINS     8192           // coarse histogram bins over [0,1]
#define CAP       8192           // gather capacity per (channel, percentile)
#define GAMMA_F   0.45454547f    // (float)(1.0/2.2)
#define UNROLL    8              // batched float4 loads per iteration

// ---------------- scratch (device globals; no allocation allowed) ----------
__device__ unsigned int g_hist[NCH * NBINS];
__device__ unsigned int g_n[NCH];
__device__ int          g_bin[NCH * 2];
__device__ unsigned int g_off[NCH * 2];
__device__ unsigned int g_cnt[NCH * 2];
__device__ float        g_vals[NCH * 2 * CAP];
__device__ float        g_v[NCH * 2];

__constant__ float c_A[3] = {1.0f / 0.229f, 1.0f / 0.224f, 1.0f / 0.225f};
__constant__ float c_B[3] = {-0.485f / 0.229f, -0.456f / 0.224f, -0.406f / 0.225f};

// ---------------- K0: zero scratch ------------------------------------------
__global__ void k_zero() {
    int i = blockIdx.x * blockDim.x + threadIdx.x;
    int stride = gridDim.x * blockDim.x;
    for (int j = i; j < NCH * NBINS; j += stride) g_hist[j] = 0;
    if (i < NCH * 2) g_cnt[i] = 0;
}

__device__ __forceinline__ int bin_of(float v) {
    int b = (int)(v * (float)NBINS);
    return b > (NBINS - 1) ? (NBINS - 1) : b;   // v > 1e-4 => b >= 0
}

// ---------------- K1: coarse histogram (full read #1) -----------------------
// grid (16, NCH): each block owns a contiguous slab of 16384 float4.
__global__ void __launch_bounds__(256) k_hist(const float* __restrict__ x) {
    __shared__ unsigned int sh[NBINS];
    const int ch = blockIdx.y;
    const float4* p = (const float4*)(x + (size_t)ch * HW) + blockIdx.x * 16384;
    const int tid = threadIdx.x;

    #pragma unroll
    for (int i = tid; i < NBINS; i += 256) sh[i] = 0;
    __syncthreads();

    for (int it = 0; it < 16384 / (256 * UNROLL); it++) {
        float4 v[UNROLL];
        #pragma unroll
        for (int j = 0; j < UNROLL; j++)
            v[j] = p[it * 256 * UNROLL + j * 256 + tid];
        #pragma unroll
        for (int j = 0; j < UNROLL; j++) {
            if (v[j].x > 1e-4f) atomicAdd(&sh[bin_of(v[j].x)], 1u);
            if (v[j].y > 1e-4f) atomicAdd(&sh[bin_of(v[j].y)], 1u);
            if (v[j].z > 1e-4f) atomicAdd(&sh[bin_of(v[j].z)], 1u);
            if (v[j].w > 1e-4f) atomicAdd(&sh[bin_of(v[j].w)], 1u);
        }
    }
    __syncthreads();

    #pragma unroll
    for (int i = tid; i < NBINS; i += 256) {
        unsigned int c = sh[i];
        if (c) atomicAdd(&g_hist[ch * NBINS + i], c);
    }
}

// ---------------- K2: find coarse bin + offset for both ranks ---------------
__global__ void __launch_bounds__(256) k_select() {
    const int ch = blockIdx.x;
    __shared__ unsigned int part[256];
    __shared__ unsigned int excl[256];
    __shared__ unsigned int sh_n;
    __shared__ unsigned int r[2];

    const int t = threadIdx.x;
    const int BPT = NBINS / 256;
    unsigned int s = 0;
    for (int j = 0; j < BPT; j++) s += g_hist[ch * NBINS + t * BPT + j];
    part[t] = s;
    __syncthreads();

    if (t == 0) {
        unsigned int run = 0;
        for (int i = 0; i < 256; i++) { excl[i] = run; run += part[i]; }
        unsigned int n = run;
        sh_n = n;
        g_n[ch] = n;
        if (n == 0) {
            g_bin[ch * 2] = -1; g_bin[ch * 2 + 1] = -1;
            r[0] = 0; r[1] = 0;
        } else {
            unsigned long long k2  = (2ull  * n) / 100ull + 1ull; if (k2  > n) k2  = n;
            unsigned long long k98 = (98ull * n) / 100ull + 1ull; if (k98 > n) k98 = n;
            r[0] = (unsigned int)(k2 - 1);
            r[1] = (unsigned int)(k98 - 1);
        }
    }
    __syncthreads();
    if (sh_n == 0) return;

    for (int w = 0; w < 2; w++) {
        unsigned int rk = r[w];
        if (rk >= excl[t] && rk < excl[t] + part[t]) {
            unsigned int run = excl[t];
            for (int j = 0; j < BPT; j++) {
                unsigned int h = g_hist[ch * NBINS + t * BPT + j];
                if (rk < run + h) {
                    g_bin[ch * 2 + w] = t * BPT + j;
                    g_off[ch * 2 + w] = rk - run;
                    break;
                }
                run += h;
            }
        }
    }
}

// ---------------- K3: gather candidates (full read #2) ----------------------
// grid (128, NCH): each block owns 2048 float4, single batched iteration.
__global__ void __launch_bounds__(256) k_gather(const float* __restrict__ x) {
    const int ch = blockIdx.y;
    const int b2  = g_bin[ch * 2];
    const int b98 = g_bin[ch * 2 + 1];
    const float4* p = (const float4*)(x + (size_t)ch * HW) + blockIdx.x * (256 * UNROLL);
    const int tid = threadIdx.x;

    float4 v[UNROLL];
    #pragma unroll
    for (int j = 0; j < UNROLL; j++)
        v[j] = p[j * 256 + tid];

    #pragma unroll
    for (int j = 0; j < UNROLL; j++) {
        float a[4] = {v[j].x, v[j].y, v[j].z, v[j].w};
        #pragma unroll
        for (int q = 0; q < 4; q++) {
            float f = a[q];
            if (f > 1e-4f) {
                int b = bin_of(f);
                if (b == b2) {
                    unsigned int pz = atomicAdd(&g_cnt[ch * 2], 1u);
                    if (pz < CAP) g_vals[(size_t)(ch * 2) * CAP + pz] = f;
                }
                if (b == b98) {
                    unsigned int pz = atomicAdd(&g_cnt[ch * 2 + 1], 1u);
                    if (pz < CAP) g_vals[(size_t)(ch * 2 + 1) * CAP + pz] = f;
                }
            }
        }
    }
}

// ---------------- K3b: exact rank-select among gathered values --------------
__global__ void __launch_bounds__(256) k_kth() {
    const int slot = blockIdx.x;        // 0..95 : (ch, which)
    __shared__ float sv[CAP];
    const int bin = g_bin[slot];
    if (bin < 0) {
        if (threadIdx.x == 0) g_v[slot] = (slot & 1) ? 1.0f : 0.0f;
        return;
    }
    const unsigned int cnt = g_cnt[slot];
    const unsigned int m   = cnt < CAP ? cnt : CAP;
    const unsigned int off = g_off[slot];

    for (unsigned int i = threadIdx.x; i < m; i += blockDim.x)
        sv[i] = g_vals[(size_t)slot * CAP + i];
    __syncthreads();

    if (off >= m) {
        if (threadIdx.x == 0)
            g_v[slot] = ((float)bin + (cnt ? (float)off / (float)cnt : 0.5f)) / (float)NBINS;
        return;
    }
    for (unsigned int i = threadIdx.x; i < m; i += blockDim.x) {
        float vi = sv[i];
        unsigned int less = 0, eqb = 0;
        for (unsigned int j = 0; j < m; j++) {
            float vj = sv[j];
            less += (vj < vi);
            eqb  += (vj == vi) && (j < i);
        }
        if (less + eqb == off) g_v[slot] = vi;   // exactly one writer
    }
}

// ---------------- K4: fused normalize + gamma + ImageNet --------------------
__device__ __forceinline__ float fastpow_g(float y) {
    float l, e;
    asm("lg2.approx.f32 %0, %1;" : "=f"(l) : "f"(y));
    asm("ex2.approx.f32 %0, %1;" : "=f"(e) : "f"(l * GAMMA_F));
    return e;
}

// grid (128, NCH): each block owns 2048 float4, batched loads then stores.
__global__ void __launch_bounds__(256) k_norm(const float* __restrict__ x,
                                              float* __restrict__ out) {
    const int ch = blockIdx.y;
    const int c  = ch - (ch / 3) * 3;
    const unsigned int n = g_n[ch];
    const float v2  = g_v[ch * 2];
    const float v98 = g_v[ch * 2 + 1];
    const float minv = (n > 100u) ? v2  : 0.0f;
    const float maxv = (n > 100u) ? v98 : 1.0f;
    float scale = maxv - minv;
    if (scale < 1e-6f) scale = 1e-6f;
    const float inv = 1.0f / scale;
    const float A = c_A[c], Bc = c_B[c];

    const size_t off = (size_t)ch * HW;
    const float4* p = (const float4*)(x + off) + blockIdx.x * (256 * UNROLL);
    float4* qo = (float4*)(out + off) + blockIdx.x * (256 * UNROLL);
    const int tid = threadIdx.x;

    float4 v[UNROLL];
    #pragma unroll
    for (int j = 0; j < UNROLL; j++)
        v[j] = p[j * 256 + tid];

    #pragma unroll
    for (int j = 0; j < UNROLL; j++) {
        float y0 = __saturatef((v[j].x - minv) * inv);
        float y1 = __saturatef((v[j].y - minv) * inv);
        float y2 = __saturatef((v[j].z - minv) * inv);
        float y3 = __saturatef((v[j].w - minv) * inv);
        float g0 = (y0 > 0.0f) ? fastpow_g(y0) : 0.0f;
        float g1 = (y1 > 0.0f) ? fastpow_g(y1) : 0.0f;
        float g2 = (y2 > 0.0f) ? fastpow_g(y2) : 0.0f;
        float g3 = (y3 > 0.0f) ? fastpow_g(y3) : 0.0f;
        v[j].x = fmaf(g0, A, Bc);
        v[j].y = fmaf(g1, A, Bc);
        v[j].z = fmaf(g2, A, Bc);
        v[j].w = fmaf(g3, A, Bc);
    }

    #pragma unroll
    for (int j = 0; j < UNROLL; j++)
        qo[j * 256 + tid] = v[j];
}

// ---------------- launch ----------------------------------------------------
extern "C" void kernel_launch(void* const* d_in, const int* in_sizes, int n_in,
                              void* d_out, int out_size) {
    const float* x = (const float*)d_in[0];
    float* out = (float*)d_out;
    (void)in_sizes; (void)n_in; (void)out_size;

    k_zero  <<<384, 256>>>();
    k_hist  <<<dim3(16,  NCH), 256>>>(x);
    k_select<<<NCH, 256>>>();
    k_gather<<<dim3(128, NCH), 256>>>(x);
    k_kth   <<<NCH * 2, 256>>>();
    k_norm  <<<dim3(128, NCH), 256>>>(x, out);
}